// round 14
// baseline (speedup 1.0000x reference)
#include <cuda_runtime.h>
#include <cstdint>

// Problem constants (LIFLayer_50405736186152)
constexpr int BATCH = 64;
constexpr int T     = 1000;
constexpr int IN    = 512;
constexpr int OUT   = 512;
constexpr int M     = BATCH * T;   // 64000 rows of the input GEMM

// Scratch for the input-driven current cur[b,t,o] (device global: no cudaMalloc allowed)
__device__ float g_cur[(size_t)BATCH * T * OUT];

// ---------------------------------------------------------------------------
// TF32 helpers
// ---------------------------------------------------------------------------
__device__ __forceinline__ uint32_t f2tf32(float f) {
    uint32_t u;
    asm("cvt.rna.tf32.f32 %0, %1;" : "=r"(u) : "f"(f));
    return u;
}

__device__ __forceinline__ void mma_tf32(float* d, const uint32_t* a, const uint32_t* b) {
    asm volatile(
        "mma.sync.aligned.m16n8k8.row.col.f32.tf32.tf32.f32 "
        "{%0,%1,%2,%3}, {%4,%5,%6,%7}, {%8,%9}, {%0,%1,%2,%3};\n"
        : "+f"(d[0]), "+f"(d[1]), "+f"(d[2]), "+f"(d[3])
        : "r"(a[0]), "r"(a[1]), "r"(a[2]), "r"(a[3]),
          "r"(b[0]), "r"(b[1]));
}

// ---------------------------------------------------------------------------
// GEMM: g_cur[m, n] = sum_k X[m, k] * W[n, k] + bias[n]
// Block tile 128x128, K-tile 32, 512 threads (16 warps as 4(m) x 4(n)).
// Warp tile 32x32: 2 m-tiles x 4 n-tiles of m16n8k8.
//
// Round-12: software pipeline with register staging, made viable by halving
// the per-warp tile (acc 64->32 regs, staging 32->16 regs): ~100 regs total,
// no spills under the 128-reg cap. tf32 conversion stays at staging time
// (16 cvt/thread/K-tile, done ONCE per smem word — R11's fragment-path cvt
// tripled conversion work and regressed). One __syncthreads per K-tile:
//   LDG(kt+1) -> 32 MMAs from smem[cur] -> cvt+STS128 into smem[cur^1] -> bar
// ---------------------------------------------------------------------------
constexpr int BKP = 36;   // padded K stride in smem words (bank = 4r+q: conflict-free)

__global__ void __launch_bounds__(512, 1)
gemm_tf32_kernel(const float* __restrict__ X,
                 const float* __restrict__ W,
                 const float* __restrict__ bias) {
    __shared__ __align__(16) uint32_t As[2][128 * BKP];
    __shared__ __align__(16) uint32_t Bs[2][128 * BKP];

    const int tid  = threadIdx.x;
    const int lane = tid & 31;
    const int warp = tid >> 5;         // 0..15
    const int warp_m = warp & 3;       // 0..3  -> 32 rows each
    const int warp_n = warp >> 2;      // 0..3  -> 32 cols each
    const int q = lane & 3;
    const int r = lane >> 2;

    const int mtile = blockIdx.y;      // 0..499
    const int ntile = blockIdx.x;      // 0..3

    const float* Ag = X + (size_t)mtile * 128 * IN;
    const float* Bg = W + (size_t)ntile * 128 * IN;

    // Per-thread staging slots: 2 x float4 for A, 2 x float4 for B per K-tile.
    int srow[2], sc4[2];
#pragma unroll
    for (int i = 0; i < 2; i++) {
        int id  = tid + i * 512;       // 0..1023 float4 slots per tensor
        srow[i] = id >> 3;
        sc4[i]  = (id & 7) * 4;
    }

    float4 ra[2], rb[2];

    auto ldg_tile = [&](int kt) {
        const int k0 = kt * 32;
#pragma unroll
        for (int i = 0; i < 2; i++) {
            ra[i] = *(const float4*)(Ag + (size_t)srow[i] * IN + k0 + sc4[i]);
            rb[i] = *(const float4*)(Bg + (size_t)srow[i] * IN + k0 + sc4[i]);
        }
    };
    auto sts_tile = [&](int buf) {
#pragma unroll
        for (int i = 0; i < 2; i++) {
            uint4 ua = make_uint4(f2tf32(ra[i].x), f2tf32(ra[i].y),
                                  f2tf32(ra[i].z), f2tf32(ra[i].w));
            *(uint4*)&As[buf][srow[i] * BKP + sc4[i]] = ua;
            uint4 ub = make_uint4(f2tf32(rb[i].x), f2tf32(rb[i].y),
                                  f2tf32(rb[i].z), f2tf32(rb[i].w));
            *(uint4*)&Bs[buf][srow[i] * BKP + sc4[i]] = ub;
        }
    };

    float acc[2][4][4];
#pragma unroll
    for (int i = 0; i < 2; i++)
#pragma unroll
        for (int j = 0; j < 4; j++)
#pragma unroll
            for (int k = 0; k < 4; k++) acc[i][j][k] = 0.f;

    // Prologue: stage tile 0
    ldg_tile(0);
    sts_tile(0);
    __syncthreads();

    constexpr int NKT = IN / 32;       // 16 K-tiles
    for (int kt = 0; kt < NKT; kt++) {
        const int cur = kt & 1;

        if (kt + 1 < NKT) ldg_tile(kt + 1);   // in flight during compute

#pragma unroll
        for (int ks = 0; ks < 4; ks++) {
            const int k8 = ks * 8;
            uint32_t afr[2][4];
#pragma unroll
            for (int mt = 0; mt < 2; mt++) {
                int m0 = warp_m * 32 + mt * 16;
                afr[mt][0] = As[cur][(m0 + r) * BKP + k8 + q];
                afr[mt][1] = As[cur][(m0 + 8 + r) * BKP + k8 + q];
                afr[mt][2] = As[cur][(m0 + r) * BKP + k8 + q + 4];
                afr[mt][3] = As[cur][(m0 + 8 + r) * BKP + k8 + q + 4];
            }
            uint32_t bfr[4][2];
#pragma unroll
            for (int nt = 0; nt < 4; nt++) {
                int n0 = warp_n * 32 + nt * 8;
                bfr[nt][0] = Bs[cur][(n0 + r) * BKP + k8 + q];
                bfr[nt][1] = Bs[cur][(n0 + r) * BKP + k8 + q + 4];
            }
#pragma unroll
            for (int mt = 0; mt < 2; mt++)
#pragma unroll
                for (int nt = 0; nt < 4; nt++)
                    mma_tf32(acc[mt][nt], afr[mt], bfr[nt]);
        }

        if (kt + 1 < NKT) {
            sts_tile(cur ^ 1);   // buf cur^1 last read in iter kt-1 (sync-protected)
            __syncthreads();
        }
    }

    // Epilogue: add bias, write cur
#pragma unroll
    for (int mt = 0; mt < 2; mt++) {
        int gm = mtile * 128 + warp_m * 32 + mt * 16 + r;
#pragma unroll
        for (int nt = 0; nt < 4; nt++) {
            int gn = ntile * 128 + warp_n * 32 + nt * 8 + 2 * q;
            float b0 = bias[gn];
            float b1 = bias[gn + 1];
            float2 v01 = make_float2(acc[mt][nt][0] + b0, acc[mt][nt][1] + b1);
            float2 v23 = make_float2(acc[mt][nt][2] + b0, acc[mt][nt][3] + b1);
            *(float2*)&g_cur[(size_t)gm * OUT + gn]       = v01;
            *(float2*)&g_cur[(size_t)(gm + 8) * OUT + gn] = v23;
        }
    }
}

// ---------------------------------------------------------------------------
// Zero-fill the two z output regions (zs and z_full). The scan then only
// stores z on the (essentially nonexistent) spike steps. Net win: the zeroing
// runs full-chip at ~5.5 TB/s while the scan runs on only 64 SMs.
// ---------------------------------------------------------------------------
__global__ void __launch_bounds__(256)
zero_z_kernel(float* __restrict__ out) {
    const size_t N1 = (size_t)BATCH * T * OUT / 4;        // zs, in float4
    const size_t N2 = (size_t)BATCH * (T + 1) * OUT / 4;  // z_full, in float4
    float4* zs = (float4*)out;
    float4* zf = (float4*)(out + (size_t)BATCH * T * OUT
                               + (size_t)BATCH * (T + 1) * OUT);
    const float4 zero = make_float4(0.f, 0.f, 0.f, 0.f);
    const size_t stride = (size_t)gridDim.x * blockDim.x;
    for (size_t i = (size_t)blockIdx.x * blockDim.x + threadIdx.x;
         i < N1 + N2; i += stride) {
        if (i < N1) zs[i] = zero;
        else        zf[i - N1] = zero;
    }
}

// ---------------------------------------------------------------------------
// Sequential LIF scan. One CTA per batch element, one thread per neuron.
// PF-deep register ring keeps PF cur-loads in flight per thread; the common
// no-spike path is 1 load + 1 store + 1 BAR.RED per step (z stores are
// predicated on z != 0 against the pre-zeroed output regions).
// ---------------------------------------------------------------------------
constexpr int PF = 8;   // prefetch depth; T % PF == 0

__global__ void __launch_bounds__(512, 1)
lif_scan_kernel(const float* __restrict__ R,      // recurrent [OUT, OUT] row-major
                const float* __restrict__ decay,  // [OUT]
                float* __restrict__ out) {
    const int b = blockIdx.x;
    const int o = threadIdx.x;

    __shared__ int s_cnt;
    __shared__ int s_idx[OUT];
    if (o == 0) s_cnt = 0;

    const float kd  = decay[o];
    const float omd = 1.0f - kd;

    const float* curp = g_cur + (size_t)b * T * OUT + o;
    float* outs = out + (size_t)b * T * OUT + o;                                 // zs
    float* vful = out + (size_t)BATCH * T * OUT + (size_t)b * (T + 1) * OUT + o; // v_full
    float* zful = vful + (size_t)BATCH * (T + 1) * OUT;                          // z_full

    // t = 0 initial v slice (z slices are pre-zeroed)
    vful[0] = 0.0f;

    // Fill the prefetch ring: PF outstanding loads per thread.
    float buf[PF];
#pragma unroll
    for (int i = 0; i < PF; i++)
        buf[i] = __ldcs(curp + (size_t)i * OUT);

    float v = 0.0f, z = 0.0f;
    int cnt_prev = 0;
    __syncthreads();   // covers s_cnt init

    for (int tb = 0; tb < T; tb += PF) {
#pragma unroll
        for (int u = 0; u < PF; u++) {
            const int t = tb + u;
            float c = buf[u];
            // refill this slot PF steps ahead (keeps PF loads in flight)
            if (t + PF < T)
                buf[u] = __ldcs(curp + (size_t)(t + PF) * OUT);

            float soma = c;
            if (cnt_prev > 0) {           // uniform branch (from BAR.RED)
                // Lazily build the spike list from last step's z.
                if (z != 0.0f) {
                    int p = atomicAdd(&s_cnt, 1);
                    s_idx[p] = o;
                }
                __syncthreads();          // list complete
                for (int j = 0; j < cnt_prev; j++)
                    soma += R[(size_t)o * OUT + s_idx[j]];
                __syncthreads();          // all reads done before list reuse
                if (o == 0) s_cnt = 0;    // ordered vs next atomicAdd by the
                                          // BAR.RED at the end of this step
            }

            v = v * (1.0f - z);           // detached reset
            v = kd * v + omd * soma;
            z = (v >= 1.0f) ? 1.0f : 0.0f;

            __stcs(vful + (size_t)(t + 1) * OUT, v);
            if (z != 0.0f) {              // regions pre-zeroed; spikes are rare
                __stcs(outs + (size_t)t * OUT, z);
                __stcs(zful + (size_t)(t + 1) * OUT, z);
            }

            cnt_prev = __syncthreads_count(z != 0.0f);
        }
    }
}

// ---------------------------------------------------------------------------
// Launch
// ---------------------------------------------------------------------------
extern "C" void kernel_launch(void* const* d_in, const int* in_sizes, int n_in,
                              void* d_out, int out_size) {
    const float* x    = (const float*)d_in[0];  // [B, T, IN]
    const float* w    = (const float*)d_in[1];  // [OUT, IN]
    const float* bias = (const float*)d_in[2];  // [OUT]
    const float* rec  = (const float*)d_in[3];  // [OUT, OUT]
    const float* dec  = (const float*)d_in[4];  // [OUT]
    float* out = (float*)d_out;

    zero_z_kernel<<<148 * 32, 256>>>(out);

    dim3 ggrid(OUT / 128, M / 128);   // (4, 500)
    gemm_tf32_kernel<<<ggrid, 512>>>(x, w, bias);
    lif_scan_kernel<<<BATCH, 512>>>(rec, dec, out);
}

// round 15
// speedup vs baseline: 1.8725x; 1.8725x over previous
#include <cuda_runtime.h>
#include <cstdint>

// Problem constants (LIFLayer_50405736186152)
constexpr int BATCH = 64;
constexpr int T     = 1000;
constexpr int IN    = 512;
constexpr int OUT   = 512;
constexpr int M     = BATCH * T;   // 64000 rows of the input GEMM

// Scratch for the input-driven current cur[b,t,o] (device global: no cudaMalloc allowed)
__device__ float g_cur[(size_t)BATCH * T * OUT];

// ---------------------------------------------------------------------------
// TF32 helpers
// ---------------------------------------------------------------------------
__device__ __forceinline__ uint32_t f2tf32(float f) {
    uint32_t u;
    asm("cvt.rna.tf32.f32 %0, %1;" : "=r"(u) : "f"(f));
    return u;
}

__device__ __forceinline__ void mma_tf32(float* d, const uint32_t* a, const uint32_t* b) {
    asm volatile(
        "mma.sync.aligned.m16n8k8.row.col.f32.tf32.tf32.f32 "
        "{%0,%1,%2,%3}, {%4,%5,%6,%7}, {%8,%9}, {%0,%1,%2,%3};\n"
        : "+f"(d[0]), "+f"(d[1]), "+f"(d[2]), "+f"(d[3])
        : "r"(a[0]), "r"(a[1]), "r"(a[2]), "r"(a[3]),
          "r"(b[0]), "r"(b[1]));
}

// ---------------------------------------------------------------------------
// GEMM (restored VERBATIM from the R5 kernel that measured 258 us).
// 256 threads, occupancy 2: the two co-resident CTAs pipeline each other
// (one stages while the other runs MMAs). R7/R11/R14 all regressed by
// breaking exactly this property — do not touch.
// ---------------------------------------------------------------------------
constexpr int BKP = 36;   // padded K stride in smem (bank-conflict-free: bank = 4r+q)

__global__ void __launch_bounds__(256, 2)
gemm_tf32_kernel(const float* __restrict__ X,
                 const float* __restrict__ W,
                 const float* __restrict__ bias) {
    __shared__ uint32_t As[128 * BKP];
    __shared__ uint32_t Bs[128 * BKP];

    const int tid  = threadIdx.x;
    const int lane = tid & 31;
    const int warp = tid >> 5;
    const int warp_m = warp & 3;       // 0..3  -> 32 rows each
    const int warp_n = warp >> 2;      // 0..1  -> 64 cols each
    const int q = lane & 3;
    const int r = lane >> 2;

    const int mtile = blockIdx.y;      // 0..499
    const int ntile = blockIdx.x;      // 0..3

    const float* Ag = X + (size_t)mtile * 128 * IN;
    const float* Bg = W + (size_t)ntile * 128 * IN;

    float acc[2][8][4];
#pragma unroll
    for (int i = 0; i < 2; i++)
#pragma unroll
        for (int j = 0; j < 8; j++)
#pragma unroll
            for (int k = 0; k < 4; k++) acc[i][j][k] = 0.f;

    for (int kt = 0; kt < IN / 32; kt++) {
        const int k0 = kt * 32;
        __syncthreads();
        // Stage A and B tiles (128 rows x 32 k), converting to tf32.
#pragma unroll
        for (int i = 0; i < 4; i++) {
            int id  = tid + i * 256;       // 0..1023 float4 slots
            int row = id >> 3;
            int c4  = (id & 7) * 4;
            float4 av = *(const float4*)(Ag + (size_t)row * IN + k0 + c4);
            uint32_t* da = &As[row * BKP + c4];
            da[0] = f2tf32(av.x); da[1] = f2tf32(av.y);
            da[2] = f2tf32(av.z); da[3] = f2tf32(av.w);
            float4 bv = *(const float4*)(Bg + (size_t)row * IN + k0 + c4);
            uint32_t* db = &Bs[row * BKP + c4];
            db[0] = f2tf32(bv.x); db[1] = f2tf32(bv.y);
            db[2] = f2tf32(bv.z); db[3] = f2tf32(bv.w);
        }
        __syncthreads();

#pragma unroll
        for (int ks = 0; ks < 4; ks++) {
            const int k8 = ks * 8;
            uint32_t afr[2][4];
#pragma unroll
            for (int mt = 0; mt < 2; mt++) {
                int m0 = warp_m * 32 + mt * 16;
                afr[mt][0] = As[(m0 + r) * BKP + k8 + q];
                afr[mt][1] = As[(m0 + 8 + r) * BKP + k8 + q];
                afr[mt][2] = As[(m0 + r) * BKP + k8 + q + 4];
                afr[mt][3] = As[(m0 + 8 + r) * BKP + k8 + q + 4];
            }
            uint32_t bfr[8][2];
#pragma unroll
            for (int nt = 0; nt < 8; nt++) {
                int n0 = warp_n * 64 + nt * 8;
                bfr[nt][0] = Bs[(n0 + r) * BKP + k8 + q];
                bfr[nt][1] = Bs[(n0 + r) * BKP + k8 + q + 4];
            }
#pragma unroll
            for (int mt = 0; mt < 2; mt++)
#pragma unroll
                for (int nt = 0; nt < 8; nt++)
                    mma_tf32(acc[mt][nt], afr[mt], bfr[nt]);
        }
    }

    // Epilogue: add bias, write cur
#pragma unroll
    for (int mt = 0; mt < 2; mt++) {
        int gm = mtile * 128 + warp_m * 32 + mt * 16 + r;
#pragma unroll
        for (int nt = 0; nt < 8; nt++) {
            int gn = ntile * 128 + warp_n * 64 + nt * 8 + 2 * q;
            float b0 = bias[gn];
            float b1 = bias[gn + 1];
            float2 v01 = make_float2(acc[mt][nt][0] + b0, acc[mt][nt][1] + b1);
            float2 v23 = make_float2(acc[mt][nt][2] + b0, acc[mt][nt][3] + b1);
            *(float2*)&g_cur[(size_t)gm * OUT + gn]       = v01;
            *(float2*)&g_cur[(size_t)(gm + 8) * OUT + gn] = v23;
        }
    }
}

// ---------------------------------------------------------------------------
// Zero-fill the two z output regions (zs and z_full) at full-chip bandwidth,
// so the scan only stores z on (essentially nonexistent) spike steps.
// ---------------------------------------------------------------------------
__global__ void __launch_bounds__(256)
zero_z_kernel(float* __restrict__ out) {
    const size_t N1 = (size_t)BATCH * T * OUT / 4;        // zs, in float4
    const size_t N2 = (size_t)BATCH * (T + 1) * OUT / 4;  // z_full, in float4
    float4* zs = (float4*)out;
    float4* zf = (float4*)(out + (size_t)BATCH * T * OUT
                               + (size_t)BATCH * (T + 1) * OUT);
    const float4 zero = make_float4(0.f, 0.f, 0.f, 0.f);
    const size_t stride = (size_t)gridDim.x * blockDim.x;
    for (size_t i = (size_t)blockIdx.x * blockDim.x + threadIdx.x;
         i < N1 + N2; i += stride) {
        if (i < N1) zs[i] = zero;
        else        zf[i - N1] = zero;
    }
}

// ---------------------------------------------------------------------------
// Sequential LIF scan with SPECULATIVE WINDOWS.
//
// The per-step __syncthreads_count existed only to communicate spikes, and
// spikes are ~11-sigma events. So: run WIN=50 steps with NO barriers,
// assuming no incoming recurrent input (each thread's own reset is still
// exact); at window end do ONE __syncthreads_count(spiked_in_window).
//  - count == 0 (always in practice): the window was exact; continue.
//  - count  > 0: roll back saved (v, z) and replay the window with the full
//    per-step exact protocol (spike list + recurrent matvec + unconditional
//    stores that overwrite any speculative stores).
// Barriers drop from 1000 to 20; the steady-state step is 1 load + 2 FMA +
// 1 store, making the scan memory-bound.
// ---------------------------------------------------------------------------
constexpr int PF  = 10;  // prefetch ring depth (static indexing: WIN % PF == 0)
constexpr int WIN = 50;  // speculation window (T % WIN == 0)

__global__ void __launch_bounds__(512, 1)
lif_scan_kernel(const float* __restrict__ R,      // recurrent [OUT, OUT] row-major
                const float* __restrict__ decay,  // [OUT]
                float* __restrict__ out) {
    const int b = blockIdx.x;
    const int o = threadIdx.x;

    __shared__ int s_cnt;
    __shared__ int s_idx[OUT];
    if (o == 0) s_cnt = 0;

    const float kd  = decay[o];
    const float omd = 1.0f - kd;

    const float* curp = g_cur + (size_t)b * T * OUT + o;
    float* outs = out + (size_t)b * T * OUT + o;                                 // zs
    float* vful = out + (size_t)BATCH * T * OUT + (size_t)b * (T + 1) * OUT + o; // v_full
    float* zful = vful + (size_t)BATCH * (T + 1) * OUT;                          // z_full

    // t = 0 initial v slice (z slices are pre-zeroed)
    vful[0] = 0.0f;

    // Fill the prefetch ring: PF outstanding loads per thread.
    float buf[PF];
#pragma unroll
    for (int i = 0; i < PF; i++)
        buf[i] = __ldcs(curp + (size_t)i * OUT);

    float v = 0.0f, z = 0.0f;
    int cnt_prev = 0;
    __syncthreads();   // covers s_cnt init

    for (int w0 = 0; w0 < T; w0 += WIN) {
        bool ring_ok = false;   // ring advanced through this window?
        bool need_exact = true;

        if (cnt_prev == 0) {
            // ---- speculative, barrier-free window ----
            const float v_save = v, z_save = z;
            int spiked = 0;
            for (int g = 0; g < WIN; g += PF) {
#pragma unroll
                for (int u = 0; u < PF; u++) {
                    const int t = w0 + g + u;
                    float c = buf[u];
                    if (t + PF < T)
                        buf[u] = __ldcs(curp + (size_t)(t + PF) * OUT);

                    v = v * (1.0f - z);          // own reset: exact
                    v = kd * v + omd * c;        // assumes no incoming spikes
                    z = (v >= 1.0f) ? 1.0f : 0.0f;
                    spiked |= (z != 0.0f);

                    __stcs(vful + (size_t)(t + 1) * OUT, v);
                    if (z != 0.0f) {             // regions pre-zeroed
                        __stcs(outs + (size_t)t * OUT, z);
                        __stcs(zful + (size_t)(t + 1) * OUT, z);
                    }
                }
            }
            ring_ok = true;
            const int cnt_win = __syncthreads_count(spiked);
            if (cnt_win == 0) {
                cnt_prev = 0;      // last step of window had no spike
                need_exact = false;
            } else {
                v = v_save; z = z_save;   // roll back; cnt_prev still 0
            }
        }

        if (need_exact) {
            // ---- exact per-step replay (rare path) ----
            for (int t = w0; t < w0 + WIN; t++) {
                float soma = __ldcs(curp + (size_t)t * OUT);
                if (cnt_prev > 0) {       // uniform (from BAR.RED)
                    if (z != 0.0f) {
                        int p = atomicAdd(&s_cnt, 1);
                        s_idx[p] = o;
                    }
                    __syncthreads();      // list complete
                    for (int j = 0; j < cnt_prev; j++)
                        soma += R[(size_t)o * OUT + s_idx[j]];
                    __syncthreads();      // reads done before list reuse
                    if (o == 0) s_cnt = 0;
                }
                v = v * (1.0f - z);
                v = kd * v + omd * soma;
                z = (v >= 1.0f) ? 1.0f : 0.0f;

                // unconditional stores overwrite speculative values
                __stcs(vful + (size_t)(t + 1) * OUT, v);
                __stcs(outs + (size_t)t * OUT, z);
                __stcs(zful + (size_t)(t + 1) * OUT, z);

                cnt_prev = __syncthreads_count(z != 0.0f);
            }
            if (!ring_ok) {
                // spec was skipped: refill the ring for the next window
#pragma unroll
                for (int i = 0; i < PF; i++)
                    if (w0 + WIN + i < T)
                        buf[i] = __ldcs(curp + (size_t)(w0 + WIN + i) * OUT);
            }
        }
    }
}

// ---------------------------------------------------------------------------
// Launch
// ---------------------------------------------------------------------------
extern "C" void kernel_launch(void* const* d_in, const int* in_sizes, int n_in,
                              void* d_out, int out_size) {
    const float* x    = (const float*)d_in[0];  // [B, T, IN]
    const float* w    = (const float*)d_in[1];  // [OUT, IN]
    const float* bias = (const float*)d_in[2];  // [OUT]
    const float* rec  = (const float*)d_in[3];  // [OUT, OUT]
    const float* dec  = (const float*)d_in[4];  // [OUT]
    float* out = (float*)d_out;

    zero_z_kernel<<<148 * 32, 256>>>(out);

    dim3 ggrid(OUT / 128, M / 128);   // (4, 500)
    gemm_tf32_kernel<<<ggrid, 256>>>(x, w, bias);
    lif_scan_kernel<<<BATCH, 512>>>(rec, dec, out);
}

// round 17
// speedup vs baseline: 2.1304x; 1.1377x over previous
#include <cuda_runtime.h>
#include <cuda_fp16.h>
#include <cstdint>

// Problem constants (LIFLayer_50405736186152)
constexpr int BATCH = 64;
constexpr int T     = 1000;
constexpr int IN    = 512;
constexpr int OUT   = 512;
constexpr int M     = BATCH * T;   // 64000 rows of the input GEMM

// Scratch for the input-driven current cur[b,t,o] (device global: no cudaMalloc allowed)
__device__ float g_cur[(size_t)BATCH * T * OUT];

// ---------------------------------------------------------------------------
// fp16 MMA helper: m16n8k16 row.col, fp32 accumulate.
// fp16 mantissa (10 bits) == tf32 mantissa -> same rounding error as the
// tf32 path (measured 3.0e-4), at 2x the FLOP per instruction.
// ---------------------------------------------------------------------------
__device__ __forceinline__ void mma_f16(float* d, const uint32_t* a, const uint32_t* b) {
    asm volatile(
        "mma.sync.aligned.m16n8k16.row.col.f32.f16.f16.f32 "
        "{%0,%1,%2,%3}, {%4,%5,%6,%7}, {%8,%9}, {%0,%1,%2,%3};\n"
        : "+f"(d[0]), "+f"(d[1]), "+f"(d[2]), "+f"(d[3])
        : "r"(a[0]), "r"(a[1]), "r"(a[2]), "r"(a[3]),
          "r"(b[0]), "r"(b[1]));
}

__device__ __forceinline__ uint32_t h2bits(__half2 h) {
    return *(uint32_t*)&h;
}

// ---------------------------------------------------------------------------
// GEMM: g_cur[m, n] = sum_k X[m, k] * W[n, k] + bias[n]
// Structure IDENTICAL to the proven R5 kernel (256 threads, occupancy 2 —
// the two co-resident CTAs pipeline each other; R7/R11/R14 all regressed by
// breaking this). Only the datatype changes: smem holds fp16x2 words, inner
// loop is 2 x m16n8k16 steps per 32-wide K-tile (32 MMAs vs 64 tf32 MMAs).
// ---------------------------------------------------------------------------
constexpr int BKW = 20;   // padded row stride in 32-bit words (16 data + 4 pad)
                          // conflict-free: (20*drow) % 32 never in {0..3} for drow 1..7

__global__ void __launch_bounds__(256, 2)
gemm_f16_kernel(const float* __restrict__ X,
                const float* __restrict__ W,
                const float* __restrict__ bias) {
    __shared__ __align__(16) uint32_t As[128 * BKW];
    __shared__ __align__(16) uint32_t Bs[128 * BKW];

    const int tid  = threadIdx.x;
    const int lane = tid & 31;
    const int warp = tid >> 5;
    const int warp_m = warp & 3;       // 0..3  -> 32 rows each
    const int warp_n = warp >> 2;      // 0..1  -> 64 cols each
    const int q = lane & 3;
    const int r = lane >> 2;

    const int mtile = blockIdx.y;      // 0..499
    const int ntile = blockIdx.x;      // 0..3

    const float* Ag = X + (size_t)mtile * 128 * IN;
    const float* Bg = W + (size_t)ntile * 128 * IN;

    float acc[2][8][4];
#pragma unroll
    for (int i = 0; i < 2; i++)
#pragma unroll
        for (int j = 0; j < 8; j++)
#pragma unroll
            for (int k = 0; k < 4; k++) acc[i][j][k] = 0.f;

    for (int kt = 0; kt < IN / 32; kt++) {
        const int k0 = kt * 32;
        __syncthreads();
        // Stage A and B tiles (128 rows x 32 k), converting to fp16x2.
#pragma unroll
        for (int i = 0; i < 4; i++) {
            int id  = tid + i * 256;       // 0..1023 float4 slots
            int row = id >> 3;
            int f4  = id & 7;              // float4 index within the 32-k row
            float4 av = *(const float4*)(Ag + (size_t)row * IN + k0 + f4 * 4);
            uint2 ua = make_uint2(h2bits(__floats2half2_rn(av.x, av.y)),
                                  h2bits(__floats2half2_rn(av.z, av.w)));
            *(uint2*)&As[row * BKW + f4 * 2] = ua;
            float4 bv = *(const float4*)(Bg + (size_t)row * IN + k0 + f4 * 4);
            uint2 ub = make_uint2(h2bits(__floats2half2_rn(bv.x, bv.y)),
                                  h2bits(__floats2half2_rn(bv.z, bv.w)));
            *(uint2*)&Bs[row * BKW + f4 * 2] = ub;
        }
        __syncthreads();

        // 2 x k16 steps cover the 32-wide K-tile.
#pragma unroll
        for (int ks = 0; ks < 2; ks++) {
            const int k8 = ks * 8;         // word offset: 8 words = 16 fp16
            uint32_t afr[2][4];
#pragma unroll
            for (int mt = 0; mt < 2; mt++) {
                int m0 = warp_m * 32 + mt * 16;
                afr[mt][0] = As[(m0 + r) * BKW + k8 + q];
                afr[mt][1] = As[(m0 + 8 + r) * BKW + k8 + q];
                afr[mt][2] = As[(m0 + r) * BKW + k8 + q + 4];
                afr[mt][3] = As[(m0 + 8 + r) * BKW + k8 + q + 4];
            }
            uint32_t bfr[8][2];
#pragma unroll
            for (int nt = 0; nt < 8; nt++) {
                int n0 = warp_n * 64 + nt * 8;
                bfr[nt][0] = Bs[(n0 + r) * BKW + k8 + q];
                bfr[nt][1] = Bs[(n0 + r) * BKW + k8 + q + 4];
            }
#pragma unroll
            for (int mt = 0; mt < 2; mt++)
#pragma unroll
                for (int nt = 0; nt < 8; nt++)
                    mma_f16(acc[mt][nt], afr[mt], bfr[nt]);
        }
    }

    // Epilogue: add bias, write cur (same accumulator layout as tf32 path)
#pragma unroll
    for (int mt = 0; mt < 2; mt++) {
        int gm = mtile * 128 + warp_m * 32 + mt * 16 + r;
#pragma unroll
        for (int nt = 0; nt < 8; nt++) {
            int gn = ntile * 128 + warp_n * 64 + nt * 8 + 2 * q;
            float b0 = bias[gn];
            float b1 = bias[gn + 1];
            float2 v01 = make_float2(acc[mt][nt][0] + b0, acc[mt][nt][1] + b1);
            float2 v23 = make_float2(acc[mt][nt][2] + b0, acc[mt][nt][3] + b1);
            *(float2*)&g_cur[(size_t)gm * OUT + gn]       = v01;
            *(float2*)&g_cur[(size_t)(gm + 8) * OUT + gn] = v23;
        }
    }
}

// ---------------------------------------------------------------------------
// Zero-fill the two z output regions (zs and z_full) at full-chip bandwidth,
// so the scan only stores z on (essentially nonexistent) spike steps.
// ---------------------------------------------------------------------------
__global__ void __launch_bounds__(256)
zero_z_kernel(float* __restrict__ out) {
    const size_t N1 = (size_t)BATCH * T * OUT / 4;        // zs, in float4
    const size_t N2 = (size_t)BATCH * (T + 1) * OUT / 4;  // z_full, in float4
    float4* zs = (float4*)out;
    float4* zf = (float4*)(out + (size_t)BATCH * T * OUT
                               + (size_t)BATCH * (T + 1) * OUT);
    const float4 zero = make_float4(0.f, 0.f, 0.f, 0.f);
    const size_t stride = (size_t)gridDim.x * blockDim.x;
    for (size_t i = (size_t)blockIdx.x * blockDim.x + threadIdx.x;
         i < N1 + N2; i += stride) {
        if (i < N1) zs[i] = zero;
        else        zf[i - N1] = zero;
    }
}

// ---------------------------------------------------------------------------
// Sequential LIF scan with speculative windows (unchanged from the R15 win).
// WIN barrier-free steps assuming no incoming spikes; one BAR.RED per window;
// exact per-step replay on (11-sigma-rare) spike windows.
// ---------------------------------------------------------------------------
constexpr int PF  = 10;  // prefetch ring depth (static indexing: WIN % PF == 0)
constexpr int WIN = 50;  // speculation window (T % WIN == 0)

__global__ void __launch_bounds__(512, 1)
lif_scan_kernel(const float* __restrict__ R,      // recurrent [OUT, OUT] row-major
                const float* __restrict__ decay,  // [OUT]
                float* __restrict__ out) {
    const int b = blockIdx.x;
    const int o = threadIdx.x;

    __shared__ int s_cnt;
    __shared__ int s_idx[OUT];
    if (o == 0) s_cnt = 0;

    const float kd  = decay[o];
    const float omd = 1.0f - kd;

    const float* curp = g_cur + (size_t)b * T * OUT + o;
    float* outs = out + (size_t)b * T * OUT + o;                                 // zs
    float* vful = out + (size_t)BATCH * T * OUT + (size_t)b * (T + 1) * OUT + o; // v_full
    float* zful = vful + (size_t)BATCH * (T + 1) * OUT;                          // z_full

    vful[0] = 0.0f;   // t = 0 initial v (z slices pre-zeroed)

    float buf[PF];
#pragma unroll
    for (int i = 0; i < PF; i++)
        buf[i] = __ldcs(curp + (size_t)i * OUT);

    float v = 0.0f, z = 0.0f;
    int cnt_prev = 0;
    __syncthreads();   // covers s_cnt init

    for (int w0 = 0; w0 < T; w0 += WIN) {
        bool ring_ok = false;
        bool need_exact = true;

        if (cnt_prev == 0) {
            // ---- speculative, barrier-free window ----
            const float v_save = v, z_save = z;
            int spiked = 0;
            for (int g = 0; g < WIN; g += PF) {
#pragma unroll
                for (int u = 0; u < PF; u++) {
                    const int t = w0 + g + u;
                    float c = buf[u];
                    if (t + PF < T)
                        buf[u] = __ldcs(curp + (size_t)(t + PF) * OUT);

                    v = v * (1.0f - z);          // own reset: exact
                    v = kd * v + omd * c;        // assumes no incoming spikes
                    z = (v >= 1.0f) ? 1.0f : 0.0f;
                    spiked |= (z != 0.0f);

                    __stcs(vful + (size_t)(t + 1) * OUT, v);
                    if (z != 0.0f) {             // regions pre-zeroed
                        __stcs(outs + (size_t)t * OUT, z);
                        __stcs(zful + (size_t)(t + 1) * OUT, z);
                    }
                }
            }
            ring_ok = true;
            const int cnt_win = __syncthreads_count(spiked);
            if (cnt_win == 0) {
                cnt_prev = 0;
                need_exact = false;
            } else {
                v = v_save; z = z_save;
            }
        }

        if (need_exact) {
            // ---- exact per-step replay (rare path) ----
            for (int t = w0; t < w0 + WIN; t++) {
                float soma = __ldcs(curp + (size_t)t * OUT);
                if (cnt_prev > 0) {
                    if (z != 0.0f) {
                        int p = atomicAdd(&s_cnt, 1);
                        s_idx[p] = o;
                    }
                    __syncthreads();
                    for (int j = 0; j < cnt_prev; j++)
                        soma += R[(size_t)o * OUT + s_idx[j]];
                    __syncthreads();
                    if (o == 0) s_cnt = 0;
                }
                v = v * (1.0f - z);
                v = kd * v + omd * soma;
                z = (v >= 1.0f) ? 1.0f : 0.0f;

                __stcs(vful + (size_t)(t + 1) * OUT, v);
                __stcs(outs + (size_t)t * OUT, z);
                __stcs(zful + (size_t)(t + 1) * OUT, z);

                cnt_prev = __syncthreads_count(z != 0.0f);
            }
            if (!ring_ok) {
#pragma unroll
                for (int i = 0; i < PF; i++)
                    if (w0 + WIN + i < T)
                        buf[i] = __ldcs(curp + (size_t)(w0 + WIN + i) * OUT);
            }
        }
    }
}

// ---------------------------------------------------------------------------
// Launch
// ---------------------------------------------------------------------------
extern "C" void kernel_launch(void* const* d_in, const int* in_sizes, int n_in,
                              void* d_out, int out_size) {
    const float* x    = (const float*)d_in[0];  // [B, T, IN]
    const float* w    = (const float*)d_in[1];  // [OUT, IN]
    const float* bias = (const float*)d_in[2];  // [OUT]
    const float* rec  = (const float*)d_in[3];  // [OUT, OUT]
    const float* dec  = (const float*)d_in[4];  // [OUT]
    float* out = (float*)d_out;

    zero_z_kernel<<<148 * 32, 256>>>(out);

    dim3 ggrid(OUT / 128, M / 128);   // (4, 500)
    gemm_f16_kernel<<<ggrid, 256>>>(x, w, bias);

    lif_scan_kernel<<<BATCH, 512>>>(rec, dec, out);
}